// round 6
// baseline (speedup 1.0000x reference)
#include <cuda_runtime.h>
#include <mma.h>
#include <math.h>

using namespace nvcuda;

#define GN 50000          // nodes
#define GH 128            // hidden dim
#define EMAX 800000       // edges

// ---------------- device scratch (no allocations allowed) ----------------
__device__ float g_m  [GN * GH];       // message linear output
__device__ float g_pre[GN * GH];       // x@Wu^T (bias added in aggregate)
__device__ float g_h  [GN * GH];       // layer activations
__device__ float g_Wh [3 * GH * 256];  // tf32-hi packed weights [l][k][j]
__device__ float g_Wl [3 * GH * 256];  // tf32-lo residuals
__device__ int   g_rowptr[GN + 1];
__device__ int   g_cursor[GN];
__device__ int   g_src[EMAX];
__device__ float g_wt [EMAX];
__device__ int   g_is64;

__device__ __forceinline__ float to_tf32(float x) {
    float r;
    asm("cvt.rna.tf32.f32 %0, %1;" : "=f"(r) : "f"(x));
    return r;
}

// ---------------- dtype detection ----------------
__global__ void detect_init_kernel() { g_is64 = 1; }

__global__ void detect_kernel(const int* __restrict__ w, int E) {
    int e = blockIdx.x * blockDim.x + threadIdx.x;
    if (e < E) {
        int lo = w[2 * e];
        int hi = w[2 * e + 1];
        if (hi != 0 || lo < 0 || lo >= GN) g_is64 = 0;
    }
}

// ---------------- CSR build ----------------
__global__ void zero_rowptr_kernel() {
    int i = blockIdx.x * blockDim.x + threadIdx.x;
    if (i <= GN) g_rowptr[i] = 0;
}

__global__ void count_kernel(const int* __restrict__ w, int E) {
    int e = blockIdx.x * blockDim.x + threadIdx.x;
    if (e < E) {
        int d = g_is64 ? w[2 * E + 2 * e] : w[E + e];
        if ((unsigned)d < (unsigned)GN) atomicAdd(&g_rowptr[d + 1], 1);
    }
}

__global__ void scan_kernel() {
    __shared__ int wsum[32];
    int tid  = threadIdx.x;
    int lane = tid & 31;
    int wid  = tid >> 5;
    int carry = 0;
    for (int base = 0; base < GN + 1; base += 1024) {
        int i = base + tid;
        int v = (i < GN + 1) ? g_rowptr[i] : 0;
        #pragma unroll
        for (int o = 1; o < 32; o <<= 1) {
            int n = __shfl_up_sync(0xffffffffu, v, o);
            if (lane >= o) v += n;
        }
        if (lane == 31) wsum[wid] = v;
        __syncthreads();
        if (wid == 0) {
            int s = wsum[lane];
            #pragma unroll
            for (int o = 1; o < 32; o <<= 1) {
                int n = __shfl_up_sync(0xffffffffu, s, o);
                if (lane >= o) s += n;
            }
            wsum[lane] = s;
        }
        __syncthreads();
        int add = carry + (wid ? wsum[wid - 1] : 0);
        v += add;
        if (i < GN + 1) g_rowptr[i] = v;
        if (i < GN)     g_cursor[i] = v;
        carry += wsum[31];
        __syncthreads();
    }
}

__global__ void fill_kernel(const int* __restrict__ w,
                            const float* __restrict__ ew, int E) {
    int e = blockIdx.x * blockDim.x + threadIdx.x;
    if (e < E) {
        int s, d;
        if (g_is64) { s = w[2 * e]; d = w[2 * E + 2 * e]; }
        else        { s = w[e];     d = w[E + e]; }
        if ((unsigned)s < (unsigned)GN && (unsigned)d < (unsigned)GN) {
            int p = atomicAdd(&g_cursor[d], 1);
            g_src[p] = s;
            g_wt[p]  = ew[e];
        }
    }
}

// ---------------- pack + tf32-split weights: [l][k][j], j<128->Wm^T else Wu^T
__global__ void pack_split_kernel(const float* __restrict__ Wm,
                                  const float* __restrict__ Wu, int layer) {
    int idx = blockIdx.x * blockDim.x + threadIdx.x;   // 128*256
    if (idx < GH * 256) {
        int k = idx >> 8;
        int j = idx & 255;
        float w = (j < 128) ? Wm[j * GH + k] : Wu[(j - 128) * GH + k];
        float wh = to_tf32(w);
        float wl = to_tf32(w - wh);
        g_Wh[layer * GH * 256 + idx] = wh;
        g_Wl[layer * GH * 256 + idx] = wl;
    }
}

// ---------------- tf32 dual GEMM (3xTF32): C = A @ W
// blockIdx.y==0 -> g_m (W cols 0..127); ==1 -> g_pre (cols 128..255).
// Block: 64 rows x 128 cols. 8 warps in 4x2; warp = 16 rows x 64 cols (4 n-tiles).
// K chunked by 32: A split on the fly into smem hi/lo, B hi/lo staged from g_Wh/g_Wl.
__global__ void __launch_bounds__(256) gemm_tf32_kernel(
        const float* __restrict__ Aext, int use_gh, int layer) {
    // smem: As_h 64x32 | As_l 64x32 | Bs_h 32x128 | Bs_l 32x128 = 48KB
    __shared__ float smem_all[12288];
    float* As_h = smem_all;          // 2048 floats, ld 32
    float* As_l = smem_all + 2048;
    float* Bs_h = smem_all + 4096;   // 4096 floats, ld 128
    float* Bs_l = smem_all + 8192;

    const float* A = use_gh ? g_h : Aext;
    const float* Wh = g_Wh + (size_t)layer * GH * 256 + blockIdx.y * 128;
    const float* Wl = g_Wl + (size_t)layer * GH * 256 + blockIdx.y * 128;
    float* dst = blockIdx.y ? g_pre : g_m;

    int t    = threadIdx.x;
    int wid  = t >> 5;
    int wr   = wid & 3;        // warp row 0..3  (16 rows each)
    int wc   = wid >> 2;       // warp col 0..1  (64 cols each)
    int row0 = blockIdx.x * 64;

    wmma::fragment<wmma::accumulator, 16, 16, 8, float> acc[4];
    #pragma unroll
    for (int nt = 0; nt < 4; nt++) wmma::fill_fragment(acc[nt], 0.0f);

    for (int kc = 0; kc < 4; kc++) {
        // --- stage A (64 x 32), split hi/lo ---
        #pragma unroll
        for (int u = 0; u < 2; u++) {
            int i = u * 1024 + t * 4;          // 2048 floats
            int r = i >> 5;
            int c = i & 31;
            float4 av = make_float4(0.f, 0.f, 0.f, 0.f);
            int grow = row0 + r;
            if (grow < GN)
                av = *(const float4*)&A[(size_t)grow * GH + kc * 32 + c];
            float h0 = to_tf32(av.x), h1 = to_tf32(av.y);
            float h2 = to_tf32(av.z), h3 = to_tf32(av.w);
            *(float4*)&As_h[i] = make_float4(h0, h1, h2, h3);
            *(float4*)&As_l[i] = make_float4(to_tf32(av.x - h0), to_tf32(av.y - h1),
                                             to_tf32(av.z - h2), to_tf32(av.w - h3));
        }
        // --- stage B (32 x 128) hi/lo ---
        #pragma unroll
        for (int u = 0; u < 4; u++) {
            int i = u * 1024 + t * 4;          // 4096 floats
            int kk = i >> 7;
            int j  = i & 127;
            const float* gh = &Wh[(size_t)(kc * 32 + kk) * 256 + j];
            const float* gl = &Wl[(size_t)(kc * 32 + kk) * 256 + j];
            *(float4*)&Bs_h[i] = *(const float4*)gh;
            *(float4*)&Bs_l[i] = *(const float4*)gl;
        }
        __syncthreads();

        #pragma unroll
        for (int ks = 0; ks < 4; ks++) {
            wmma::fragment<wmma::matrix_a, 16, 16, 8, wmma::precision::tf32, wmma::row_major> ah, al;
            wmma::load_matrix_sync(ah, &As_h[(wr * 16) * 32 + ks * 8], 32);
            wmma::load_matrix_sync(al, &As_l[(wr * 16) * 32 + ks * 8], 32);
            #pragma unroll
            for (int nt = 0; nt < 4; nt++) {
                wmma::fragment<wmma::matrix_b, 16, 16, 8, wmma::precision::tf32, wmma::row_major> bh, bl;
                int coff = wc * 64 + nt * 16;
                wmma::load_matrix_sync(bh, &Bs_h[(ks * 8) * 128 + coff], 128);
                wmma::load_matrix_sync(bl, &Bs_l[(ks * 8) * 128 + coff], 128);
                wmma::mma_sync(acc[nt], ah, bh, acc[nt]);
                wmma::mma_sync(acc[nt], al, bh, acc[nt]);
                wmma::mma_sync(acc[nt], ah, bl, acc[nt]);
            }
        }
        __syncthreads();
    }

    // --- epilogue ---
    if (row0 + 64 <= GN) {
        #pragma unroll
        for (int nt = 0; nt < 4; nt++) {
            size_t off = (size_t)(row0 + wr * 16) * GH + wc * 64 + nt * 16;
            wmma::store_matrix_sync(&dst[off], acc[nt], GH, wmma::mem_row_major);
        }
    } else {
        // boundary block: stage through smem (reuse As region: 64x32), guarded copy
        float* stage = smem_all;   // 2048 floats, ld 32
        for (int nt = 0; nt < 4; nt++) {
            wmma::store_matrix_sync(&stage[(wr * 16) * 32 + wc * 16], acc[nt],
                                    32, wmma::mem_row_major);
            __syncthreads();
            #pragma unroll
            for (int u = 0; u < 2; u++) {
                int i = u * 1024 + t * 4;
                int r = i >> 5;
                int c = i & 31;
                int grow = row0 + r;
                if (grow < GN) {
                    int gcol = (c < 16 ? 0 : 64 - 16) + nt * 16 + c;  // wc=0: c<16 -> cols nt*16+c ; wc=1: c>=16 -> 64+nt*16+(c-16)
                    *(float4*)&dst[(size_t)grow * GH + gcol] = *(float4*)&stage[i];
                }
            }
            __syncthreads();
        }
    }
}

// ---------------- aggregate + bias + tanh: one warp per destination node -------
__global__ void __launch_bounds__(256) aggregate_kernel(const float* __restrict__ bu) {
    int warp = (blockIdx.x * blockDim.x + threadIdx.x) >> 5;
    int lane = threadIdx.x & 31;
    if (warp >= GN) return;
    int beg = g_rowptr[warp];
    int end = g_rowptr[warp + 1];
    float4 b4   = *(const float4*)&bu[lane * 4];
    float4 pre4 = *(const float4*)&g_pre[(size_t)warp * GH + lane * 4];
    float4 acc  = make_float4(pre4.x + b4.x, pre4.y + b4.y,
                              pre4.z + b4.z, pre4.w + b4.w);
    float4 acc2 = make_float4(0.f, 0.f, 0.f, 0.f);
    int p = beg;
    for (; p + 1 < end; p += 2) {
        int s0 = g_src[p];     float w0 = g_wt[p];
        int s1 = g_src[p + 1]; float w1 = g_wt[p + 1];
        float4 m0 = *(const float4*)&g_m[(size_t)s0 * GH + lane * 4];
        float4 m1 = *(const float4*)&g_m[(size_t)s1 * GH + lane * 4];
        acc.x  = fmaf(w0, m0.x, acc.x);  acc.y  = fmaf(w0, m0.y, acc.y);
        acc.z  = fmaf(w0, m0.z, acc.z);  acc.w  = fmaf(w0, m0.w, acc.w);
        acc2.x = fmaf(w1, m1.x, acc2.x); acc2.y = fmaf(w1, m1.y, acc2.y);
        acc2.z = fmaf(w1, m1.z, acc2.z); acc2.w = fmaf(w1, m1.w, acc2.w);
    }
    if (p < end) {
        int s = g_src[p]; float w = g_wt[p];
        float4 mv = *(const float4*)&g_m[(size_t)s * GH + lane * 4];
        acc.x = fmaf(w, mv.x, acc.x); acc.y = fmaf(w, mv.y, acc.y);
        acc.z = fmaf(w, mv.z, acc.z); acc.w = fmaf(w, mv.w, acc.w);
    }
    acc.x += acc2.x; acc.y += acc2.y; acc.z += acc2.z; acc.w += acc2.w;
    float4 r;
    r.x = tanhf(acc.x); r.y = tanhf(acc.y); r.z = tanhf(acc.z); r.w = tanhf(acc.w);
    *(float4*)&g_h[(size_t)warp * GH + lane * 4] = r;
}

// ---------------- output projection: out = h @ Wout^T + bout ----------------
__global__ void __launch_bounds__(256) out_gemm_kernel(
        const float* __restrict__ Wout, const float* __restrict__ bout,
        float* __restrict__ out) {
    __shared__ float Ws[128][32];
    __shared__ float Hs[8][128];
    int t = threadIdx.x;
    for (int i = t; i < 32 * 128; i += 256) {
        int c = i & 31;
        int k = i >> 5;
        Ws[k][c] = Wout[c * GH + k];
    }
    int row0 = blockIdx.x * 8;
    {
        int idx = t * 4;
        int r   = idx >> 7;
        int k   = idx & 127;
        float4 hv = make_float4(0.f, 0.f, 0.f, 0.f);
        if (row0 + r < GN) hv = *(const float4*)&g_h[(size_t)(row0 + r) * GH + k];
        *(float4*)&Hs[r][k] = hv;
    }
    __syncthreads();
    int w    = t >> 5;
    int lane = t & 31;
    int row  = row0 + w;
    float acc = bout[lane];
    #pragma unroll
    for (int k = 0; k < GH; k++) acc = fmaf(Hs[w][k], Ws[k][lane], acc);
    if (row < GN) out[row * 32 + lane] = acc;
}

// ---------------- launch ----------------
extern "C" void kernel_launch(void* const* d_in, const int* in_sizes, int n_in,
                              void* d_out, int out_size) {
    const float* x    = (const float*)d_in[0];
    const int*   ei   = (const int*)d_in[1];
    const float* ew   = (const float*)d_in[2];
    const float* Wm[3] = {(const float*)d_in[3], (const float*)d_in[6], (const float*)d_in[9]};
    const float* Wu[3] = {(const float*)d_in[4], (const float*)d_in[7], (const float*)d_in[10]};
    const float* bu[3] = {(const float*)d_in[5], (const float*)d_in[8], (const float*)d_in[11]};
    const float* Wout = (const float*)d_in[12];
    const float* bout = (const float*)d_in[13];
    float*       out  = (float*)d_out;

    int E = in_sizes[1] / 2;

    // weight pack/split upfront (independent of CSR build)
    for (int l = 0; l < 3; l++)
        pack_split_kernel<<<(GH * 256 + 255) / 256, 256>>>(Wm[l], Wu[l], l);

    detect_init_kernel<<<1, 1>>>();
    detect_kernel<<<(E + 255) / 256, 256>>>(ei, E);
    zero_rowptr_kernel<<<(GN + 256) / 256, 256>>>();
    count_kernel<<<(E + 255) / 256, 256>>>(ei, E);
    scan_kernel<<<1, 1024>>>();
    fill_kernel<<<(E + 255) / 256, 256>>>(ei, ew, E);

    dim3 ggrid((GN + 63) / 64, 2);
    int  agg_blocks = (GN * 32 + 255) / 256;

    for (int l = 0; l < 3; l++) {
        gemm_tf32_kernel<<<ggrid, 256>>>(x, l > 0 ? 1 : 0, l);
        aggregate_kernel<<<agg_blocks, 256>>>(bu[l]);
    }

    out_gemm_kernel<<<(GN + 7) / 8, 256>>>(Wout, bout, out);
}

// round 8
// speedup vs baseline: 2.2292x; 2.2292x over previous
#include <cuda_runtime.h>
#include <cuda_bf16.h>
#include <math.h>
#include <cstdint>

#define GN 50000          // nodes
#define GH 128            // hidden dim
#define EMAX 800000       // edges

// ---------------- device scratch (no allocations allowed) ----------------
__device__ float g_m  [GN * GH];             // message linear output
__device__ float g_pre[GN * GH];             // x@Wu^T (bias added in aggregate)
__device__ float g_h  [GN * GH];             // layer activations
__device__ __nv_bfloat16 g_Bh[3 * 256 * GH]; // [l][j][k] packed Wm|Wu rows, bf16 hi
__device__ __nv_bfloat16 g_Bl[3 * 256 * GH]; // bf16 lo residual
__device__ int   g_rowptr[GN + 1];
__device__ int   g_cursor[GN];
__device__ int   g_src[EMAX];
__device__ float g_wt [EMAX];
__device__ int   g_is64;

__device__ __forceinline__ uint32_t smem_u32(const void* p) {
    uint32_t a;
    asm("{ .reg .u64 t; cvta.to.shared.u64 t, %1; cvt.u32.u64 %0, t; }"
        : "=r"(a) : "l"(p));
    return a;
}

// ---------------- dtype detection ----------------
__global__ void detect_init_kernel() { g_is64 = 1; }

__global__ void detect_kernel(const int* __restrict__ w, int E) {
    int e = blockIdx.x * blockDim.x + threadIdx.x;
    if (e < E) {
        int lo = w[2 * e];
        int hi = w[2 * e + 1];
        if (hi != 0 || lo < 0 || lo >= GN) g_is64 = 0;
    }
}

// ---------------- CSR build ----------------
__global__ void zero_rowptr_kernel() {
    int i = blockIdx.x * blockDim.x + threadIdx.x;
    if (i <= GN) g_rowptr[i] = 0;
}

__global__ void count_kernel(const int* __restrict__ w, int E) {
    int e = blockIdx.x * blockDim.x + threadIdx.x;
    if (e < E) {
        int d = g_is64 ? w[2 * E + 2 * e] : w[E + e];
        if ((unsigned)d < (unsigned)GN) atomicAdd(&g_rowptr[d + 1], 1);
    }
}

__global__ void scan_kernel() {
    __shared__ int wsum[32];
    int tid  = threadIdx.x;
    int lane = tid & 31;
    int wid  = tid >> 5;
    int carry = 0;
    for (int base = 0; base < GN + 1; base += 1024) {
        int i = base + tid;
        int v = (i < GN + 1) ? g_rowptr[i] : 0;
        #pragma unroll
        for (int o = 1; o < 32; o <<= 1) {
            int n = __shfl_up_sync(0xffffffffu, v, o);
            if (lane >= o) v += n;
        }
        if (lane == 31) wsum[wid] = v;
        __syncthreads();
        if (wid == 0) {
            int s = wsum[lane];
            #pragma unroll
            for (int o = 1; o < 32; o <<= 1) {
                int n = __shfl_up_sync(0xffffffffu, s, o);
                if (lane >= o) s += n;
            }
            wsum[lane] = s;
        }
        __syncthreads();
        int add = carry + (wid ? wsum[wid - 1] : 0);
        v += add;
        if (i < GN + 1) g_rowptr[i] = v;
        if (i < GN)     g_cursor[i] = v;
        carry += wsum[31];
        __syncthreads();
    }
}

__global__ void fill_kernel(const int* __restrict__ w,
                            const float* __restrict__ ew, int E) {
    int e = blockIdx.x * blockDim.x + threadIdx.x;
    if (e < E) {
        int s, d;
        if (g_is64) { s = w[2 * e]; d = w[2 * E + 2 * e]; }
        else        { s = w[e];     d = w[E + e]; }
        if ((unsigned)s < (unsigned)GN && (unsigned)d < (unsigned)GN) {
            int p = atomicAdd(&g_cursor[d], 1);
            g_src[p] = s;
            g_wt[p]  = ew[e];
        }
    }
}

// ---------------- weight pack + bf16 hi/lo split: g_B*[l][j][k] ----------------
__global__ void split_b_kernel(const float* __restrict__ Wm,
                               const float* __restrict__ Wu, int layer) {
    int idx = blockIdx.x * blockDim.x + threadIdx.x;   // 256*128
    if (idx < 256 * GH) {
        int j = idx >> 7;
        int k = idx & 127;
        float w = (j < 128) ? Wm[j * GH + k] : Wu[(j - 128) * GH + k];
        __nv_bfloat16 h = __float2bfloat16_rn(w);
        __nv_bfloat16 l = __float2bfloat16_rn(w - __bfloat162float(h));
        g_Bh[(size_t)layer * 256 * GH + idx] = h;
        g_Bl[(size_t)layer * 256 * GH + idx] = l;
    }
}

// ================= mma.sync bf16 GEMM =================
// C[128 rows x 256 cols] = A[128 x 128] @ B[256 x 128]^T per CTA.
// 512 threads = 16 warps (wm 0..3, wn 0..3), warp tile 32 rows x 64 cols.
// 3-term bf16 split: AhBh + AlBh + AhBl, fp32 accumulate.
// SMEM tiles swizzled: addr(r, seg) = r*128 + ((seg ^ (r&7)) << 4), seg = 16B unit.

#define SM_AH 0          // A hi: 128 x 64 bf16 = 16KB
#define SM_AL 16384      // A lo
#define SM_BH 32768      // B hi: 256 x 64 bf16 = 32KB
#define SM_BL 65536      // B lo
#define SM_TOTAL 98304

__device__ __forceinline__ void ldsm_x4(uint32_t* r, uint32_t addr) {
    asm volatile("ldmatrix.sync.aligned.m8n8.x4.shared.b16 {%0,%1,%2,%3}, [%4];"
                 : "=r"(r[0]), "=r"(r[1]), "=r"(r[2]), "=r"(r[3]) : "r"(addr));
}
__device__ __forceinline__ void ldsm_x2(uint32_t* r, uint32_t addr) {
    asm volatile("ldmatrix.sync.aligned.m8n8.x2.shared.b16 {%0,%1}, [%2];"
                 : "=r"(r[0]), "=r"(r[1]) : "r"(addr));
}
__device__ __forceinline__ void mma16816(float* d, const uint32_t* a, const uint32_t* b) {
    asm volatile(
        "mma.sync.aligned.m16n8k16.row.col.f32.bf16.bf16.f32 "
        "{%0,%1,%2,%3}, {%4,%5,%6,%7}, {%8,%9}, {%0,%1,%2,%3};"
        : "+f"(d[0]), "+f"(d[1]), "+f"(d[2]), "+f"(d[3])
        : "r"(a[0]), "r"(a[1]), "r"(a[2]), "r"(a[3]), "r"(b[0]), "r"(b[1]));
}

__global__ void __launch_bounds__(512) gemm_mma_kernel(
        const float* __restrict__ Aext, int use_gh, int layer) {
    extern __shared__ char smem[];
    uint32_t sb = smem_u32(smem);
    const float* A = use_gh ? g_h : Aext;
    int t    = threadIdx.x;
    int lane = t & 31;
    int wid  = t >> 5;
    int wm   = wid & 3;      // warp row block (32 rows)
    int wn   = wid >> 2;     // warp col block (64 cols)
    int row0 = blockIdx.x * 128;

    float acc[2][8][4];
    #pragma unroll
    for (int mi = 0; mi < 2; mi++)
        #pragma unroll
        for (int nj = 0; nj < 8; nj++)
            #pragma unroll
            for (int q = 0; q < 4; q++) acc[mi][nj][q] = 0.f;

    for (int kc = 0; kc < 2; kc++) {
        if (kc) __syncthreads();
        // ---- stage A (128 rows x 64 k), fp32 -> bf16 hi/lo, swizzled ----
        #pragma unroll
        for (int it = 0; it < 2; it++) {
            int u   = t + it * 512;         // 1024 16B-units
            int r   = u >> 3;
            int seg = u & 7;
            int grow = row0 + r;
            float v[8];
            if (grow < GN) {
                const float* ap = &A[(size_t)grow * GH + kc * 64 + seg * 8];
                float4 v0 = *(const float4*)ap;
                float4 v1 = *(const float4*)(ap + 4);
                v[0]=v0.x; v[1]=v0.y; v[2]=v0.z; v[3]=v0.w;
                v[4]=v1.x; v[5]=v1.y; v[6]=v1.z; v[7]=v1.w;
            } else {
                #pragma unroll
                for (int q = 0; q < 8; q++) v[q] = 0.f;
            }
            uint32_t hp[4], lp[4];
            #pragma unroll
            for (int q = 0; q < 4; q++) {
                __nv_bfloat16 h0 = __float2bfloat16_rn(v[2*q]);
                __nv_bfloat16 h1 = __float2bfloat16_rn(v[2*q+1]);
                float l0f = v[2*q]   - __bfloat162float(h0);
                float l1f = v[2*q+1] - __bfloat162float(h1);
                __nv_bfloat162 hh = __halves2bfloat162(h0, h1);
                __nv_bfloat162 ll = __floats2bfloat162_rn(l0f, l1f);
                hp[q] = *(uint32_t*)&hh;
                lp[q] = *(uint32_t*)&ll;
            }
            uint32_t off = (uint32_t)r * 128 + (uint32_t)((seg ^ (r & 7)) << 4);
            *(uint4*)(smem + SM_AH + off) = make_uint4(hp[0], hp[1], hp[2], hp[3]);
            *(uint4*)(smem + SM_AL + off) = make_uint4(lp[0], lp[1], lp[2], lp[3]);
        }
        // ---- stage B (256 rows x 64 k), already bf16, swizzled ----
        #pragma unroll
        for (int it = 0; it < 4; it++) {
            int u   = t + it * 512;         // 2048 16B-units
            int j   = u >> 3;
            int seg = u & 7;
            size_t src = ((size_t)(layer * 256 + j)) * GH + kc * 64 + seg * 8;
            uint4 hv = *(const uint4*)&g_Bh[src];
            uint4 lv = *(const uint4*)&g_Bl[src];
            uint32_t off = (uint32_t)j * 128 + (uint32_t)((seg ^ (j & 7)) << 4);
            *(uint4*)(smem + SM_BH + off) = hv;
            *(uint4*)(smem + SM_BL + off) = lv;
        }
        __syncthreads();

        // ---- compute: 4 k16 steps ----
        #pragma unroll
        for (int ks = 0; ks < 4; ks++) {
            uint32_t ah[2][4], al[2][4];
            #pragma unroll
            for (int mi = 0; mi < 2; mi++) {
                int rr = wm * 32 + mi * 16 + (lane & 7) + ((lane & 8) ? 8 : 0);
                int sg = ks * 2 + ((lane >> 4) & 1);
                uint32_t off = (uint32_t)rr * 128 + (uint32_t)((sg ^ (rr & 7)) << 4);
                ldsm_x4(ah[mi], sb + SM_AH + off);
                ldsm_x4(al[mi], sb + SM_AL + off);
            }
            #pragma unroll
            for (int nj = 0; nj < 8; nj++) {
                int nn = wn * 64 + nj * 8 + (lane & 7);
                int sg = ks * 2 + ((lane >> 3) & 1);
                uint32_t off = (uint32_t)nn * 128 + (uint32_t)((sg ^ (nn & 7)) << 4);
                uint32_t bh[2], bl[2];
                ldsm_x2(bh, sb + SM_BH + off);
                ldsm_x2(bl, sb + SM_BL + off);
                #pragma unroll
                for (int mi = 0; mi < 2; mi++) {
                    mma16816(acc[mi][nj], ah[mi], bh);
                    mma16816(acc[mi][nj], al[mi], bh);
                    mma16816(acc[mi][nj], ah[mi], bl);
                }
            }
        }
    }

    // ---- epilogue ----
    int gid = lane >> 2;
    int tig = lane & 3;
    #pragma unroll
    for (int mi = 0; mi < 2; mi++) {
        int row = row0 + wm * 32 + mi * 16 + gid;
        #pragma unroll
        for (int nj = 0; nj < 8; nj++) {
            int c  = wn * 64 + nj * 8 + 2 * tig;
            float* base = (c < 128) ? g_m : g_pre;
            int cc = c & 127;
            if (row < GN) {
                float2 v0 = make_float2(acc[mi][nj][0], acc[mi][nj][1]);
                *(float2*)&base[(size_t)row * GH + cc] = v0;
            }
            if (row + 8 < GN) {
                float2 v1 = make_float2(acc[mi][nj][2], acc[mi][nj][3]);
                *(float2*)&base[(size_t)(row + 8) * GH + cc] = v1;
            }
        }
    }
}

// ---------------- aggregate + bias + tanh: one warp per destination node -------
__global__ void __launch_bounds__(256) aggregate_kernel(const float* __restrict__ bu) {
    int warp = (blockIdx.x * blockDim.x + threadIdx.x) >> 5;
    int lane = threadIdx.x & 31;
    if (warp >= GN) return;
    int beg = g_rowptr[warp];
    int end = g_rowptr[warp + 1];
    float4 b4   = *(const float4*)&bu[lane * 4];
    float4 pre4 = *(const float4*)&g_pre[(size_t)warp * GH + lane * 4];
    float4 acc  = make_float4(pre4.x + b4.x, pre4.y + b4.y,
                              pre4.z + b4.z, pre4.w + b4.w);
    float4 acc2 = make_float4(0.f, 0.f, 0.f, 0.f);
    int p = beg;
    for (; p + 1 < end; p += 2) {
        int s0 = g_src[p];     float w0 = g_wt[p];
        int s1 = g_src[p + 1]; float w1 = g_wt[p + 1];
        float4 m0 = *(const float4*)&g_m[(size_t)s0 * GH + lane * 4];
        float4 m1 = *(const float4*)&g_m[(size_t)s1 * GH + lane * 4];
        acc.x  = fmaf(w0, m0.x, acc.x);  acc.y  = fmaf(w0, m0.y, acc.y);
        acc.z  = fmaf(w0, m0.z, acc.z);  acc.w  = fmaf(w0, m0.w, acc.w);
        acc2.x = fmaf(w1, m1.x, acc2.x); acc2.y = fmaf(w1, m1.y, acc2.y);
        acc2.z = fmaf(w1, m1.z, acc2.z); acc2.w = fmaf(w1, m1.w, acc2.w);
    }
    if (p < end) {
        int s = g_src[p]; float w = g_wt[p];
        float4 mv = *(const float4*)&g_m[(size_t)s * GH + lane * 4];
        acc.x = fmaf(w, mv.x, acc.x); acc.y = fmaf(w, mv.y, acc.y);
        acc.z = fmaf(w, mv.z, acc.z); acc.w = fmaf(w, mv.w, acc.w);
    }
    acc.x += acc2.x; acc.y += acc2.y; acc.z += acc2.z; acc.w += acc2.w;
    float4 r;
    r.x = tanhf(acc.x); r.y = tanhf(acc.y); r.z = tanhf(acc.z); r.w = tanhf(acc.w);
    *(float4*)&g_h[(size_t)warp * GH + lane * 4] = r;
}

// ---------------- output projection: out = h @ Wout^T + bout ----------------
__global__ void __launch_bounds__(256) out_gemm_kernel(
        const float* __restrict__ Wout, const float* __restrict__ bout,
        float* __restrict__ out) {
    __shared__ float Ws[128][32];
    __shared__ float Hs[8][128];
    int t = threadIdx.x;
    for (int i = t; i < 32 * 128; i += 256) {
        int c = i & 31;
        int k = i >> 5;
        Ws[k][c] = Wout[c * GH + k];
    }
    int row0 = blockIdx.x * 8;
    {
        int idx = t * 4;
        int r   = idx >> 7;
        int k   = idx & 127;
        float4 hv = make_float4(0.f, 0.f, 0.f, 0.f);
        if (row0 + r < GN) hv = *(const float4*)&g_h[(size_t)(row0 + r) * GH + k];
        *(float4*)&Hs[r][k] = hv;
    }
    __syncthreads();
    int w    = t >> 5;
    int lane = t & 31;
    int row  = row0 + w;
    float acc = bout[lane];
    #pragma unroll
    for (int k = 0; k < GH; k++) acc = fmaf(Hs[w][k], Ws[k][lane], acc);
    if (row < GN) out[row * 32 + lane] = acc;
}

// ---------------- launch ----------------
extern "C" void kernel_launch(void* const* d_in, const int* in_sizes, int n_in,
                              void* d_out, int out_size) {
    const float* x    = (const float*)d_in[0];
    const int*   ei   = (const int*)d_in[1];
    const float* ew   = (const float*)d_in[2];
    const float* Wm[3] = {(const float*)d_in[3], (const float*)d_in[6], (const float*)d_in[9]};
    const float* Wu[3] = {(const float*)d_in[4], (const float*)d_in[7], (const float*)d_in[10]};
    const float* bu[3] = {(const float*)d_in[5], (const float*)d_in[8], (const float*)d_in[11]};
    const float* Wout = (const float*)d_in[12];
    const float* bout = (const float*)d_in[13];
    float*       out  = (float*)d_out;

    int E = in_sizes[1] / 2;

    cudaFuncSetAttribute(gemm_mma_kernel,
                         cudaFuncAttributeMaxDynamicSharedMemorySize, SM_TOTAL);

    for (int l = 0; l < 3; l++)
        split_b_kernel<<<(256 * GH + 255) / 256, 256>>>(Wm[l], Wu[l], l);

    detect_init_kernel<<<1, 1>>>();
    detect_kernel<<<(E + 255) / 256, 256>>>(ei, E);
    zero_rowptr_kernel<<<(GN + 256) / 256, 256>>>();
    count_kernel<<<(E + 255) / 256, 256>>>(ei, E);
    scan_kernel<<<1, 1024>>>();
    fill_kernel<<<(E + 255) / 256, 256>>>(ei, ew, E);

    int ggrid = (GN + 127) / 128;                 // 391
    int agg_blocks = (GN * 32 + 255) / 256;

    for (int l = 0; l < 3; l++) {
        gemm_mma_kernel<<<ggrid, 512, SM_TOTAL>>>(x, l > 0 ? 1 : 0, l);
        aggregate_kernel<<<agg_blocks, 256>>>(bu[l]);
    }

    out_gemm_kernel<<<(GN + 7) / 8, 256>>>(Wout, bout, out);
}